// round 2
// baseline (speedup 1.0000x reference)
#include <cuda_runtime.h>
#include <cstddef>

// Shapes (fixed by the problem)
#define B 16
#define W 256
#define S 512
#define H 768
#define L 12
#define E 256

// hidden_states: [L, B, S, H] fp32, layer stride = B*S*H
#define LAYER_STRIDE ((size_t)B * S * H)

// Block = 256 threads per (b, w) word.
//   threads [0,64):    copy W_embed[word_indices[b,w]] (E=256 fp32 = 64 float4)
//   threads [64,256):  192 threads x float4 = 768 fp32 bert span-mean
//
// Span length is 1 or 2. We ALWAYS issue 24 independent loads per thread:
// 12 from row s0 and 12 from row (s1-1). When len==1, the two rows coincide,
// so the second set are L1/L2 hits (no extra DRAM traffic) and the second
// accumulator is weighted by 0. No dynamic loop -> max front-batched MLP.
__global__ __launch_bounds__(256)
void bert_lexer_kernel(const int* __restrict__ word_indices,
                       const int* __restrict__ span_start,
                       const int* __restrict__ span_end,
                       const float* __restrict__ W_embed,
                       const float* __restrict__ hidden,
                       float* __restrict__ out)
{
    const int bw  = blockIdx.x;            // 0 .. B*W-1
    const int b   = bw >> 8;               // W = 256
    const int tid = threadIdx.x;

    float* orow = out + (size_t)bw * (E + H);

    if (tid < 64) {
        // ---- word embedding gather: 64 threads x float4 = 256 floats ----
        const int wi = word_indices[bw];
        const float4* src = reinterpret_cast<const float4*>(W_embed + (size_t)wi * E);
        float4 v = src[tid];
        __stcs(reinterpret_cast<float4*>(orow) + tid, v);
    } else {
        // ---- bert span mean: 192 threads x float4 = 768 floats ----
        const int t   = tid - 64;          // 0 .. 191
        const int s0  = span_start[bw];
        const int se  = span_end[bw];
        const int sl  = se - 1;            // last position (== s0 when len==1)
        const int len = se - s0;           // 1 or 2

        const float* p0 = hidden + ((size_t)b * S + (size_t)s0) * H + (size_t)t * 4;
        const float* p1 = hidden + ((size_t)b * S + (size_t)sl) * H + (size_t)t * 4;

        float4 a0 = make_float4(0.f, 0.f, 0.f, 0.f);
        float4 a1 = make_float4(0.f, 0.f, 0.f, 0.f);

        #pragma unroll
        for (int l = 0; l < L; ++l) {
            float4 v0 = *reinterpret_cast<const float4*>(p0 + (size_t)l * LAYER_STRIDE);
            float4 v1 = *reinterpret_cast<const float4*>(p1 + (size_t)l * LAYER_STRIDE);
            a0.x += v0.x; a0.y += v0.y; a0.z += v0.z; a0.w += v0.w;
            a1.x += v1.x; a1.y += v1.y; a1.z += v1.z; a1.w += v1.w;
        }

        const float w1  = (len > 1) ? 1.0f : 0.0f;   // drop duplicate row when len==1
        const float inv = 1.0f / (12.0f * (float)len);

        float4 r;
        r.x = (a0.x + w1 * a1.x) * inv;
        r.y = (a0.y + w1 * a1.y) * inv;
        r.z = (a0.z + w1 * a1.z) * inv;
        r.w = (a0.w + w1 * a1.w) * inv;

        __stcs(reinterpret_cast<float4*>(orow + E) + t, r);
    }
}

extern "C" void kernel_launch(void* const* d_in, const int* in_sizes, int n_in,
                              void* d_out, int out_size)
{
    const int*   word_indices = (const int*)  d_in[0];   // [B, W]
    const int*   span_start   = (const int*)  d_in[1];   // [B, W]
    const int*   span_end     = (const int*)  d_in[2];   // [B, W]
    const float* W_embed      = (const float*)d_in[3];   // [V, E]
    const float* hidden       = (const float*)d_in[4];   // [L, B, S, H]
    float*       out          = (float*)      d_out;     // [B, W, E+H]

    (void)in_sizes; (void)n_in; (void)out_size;

    bert_lexer_kernel<<<B * W, 256>>>(word_indices, span_start, span_end,
                                      W_embed, hidden, out);
}